// round 9
// baseline (speedup 1.0000x reference)
#include <cuda_runtime.h>
#include <cstdint>

// Geometry fixed by setup_inputs: (16, 4, 1024, 1024) float32
#define BATCH 16
#define HH 1024
#define WW 1024
#define HW (HH * WW)

#define TILE_W 128
#define TILE_H 64
#define THREADS 512

// Phase-1 T1 region: rows gy = y0-1 .. y0+64 (66), cols gx = x0-4 .. x0+131
// (34 quads of 4). Pitch 136 floats, float4-aligned.
#define P1ROWS (TILE_H + 2)        // 66
#define QPR 34                     // quads per row
#define SPITCH (QPR * 4)           // 136
#define NQUADS (P1ROWS * QPR)      // 2244

#define RED_X 128
#define NPART (RED_X * BATCH)      // 2048 partials

__device__ float g_partials[NPART];

// ---------------------------------------------------------------------------
// Stage 1: per-block max(|u|,|v|) partials (unconditional writes, no reset).
// Default policy: fills L2 with u,v so fused_kernel's reads hit.
// ---------------------------------------------------------------------------
__global__ __launch_bounds__(256)
void maxabs_kernel(const float* __restrict__ in) {
    const float4* __restrict__ base =
        reinterpret_cast<const float4*>(in + (size_t)blockIdx.y * 4 * HW);
    const int n4 = 2 * HW / 4;
    float m = 0.0f;
    #pragma unroll 8
    for (int i = blockIdx.x * 256 + threadIdx.x; i < n4; i += RED_X * 256) {
        float4 vv = base[i];
        m = fmaxf(m, fabsf(vv.x));
        m = fmaxf(m, fabsf(vv.y));
        m = fmaxf(m, fabsf(vv.z));
        m = fmaxf(m, fabsf(vv.w));
    }
    #pragma unroll
    for (int o = 16; o > 0; o >>= 1)
        m = fmaxf(m, __shfl_xor_sync(0xFFFFFFFFu, m, o));
    __shared__ float smax[8];
    int lane = threadIdx.x & 31, wid = threadIdx.x >> 5;
    if (lane == 0) smax[wid] = m;
    __syncthreads();
    if (threadIdx.x == 0) {
        float mm = smax[0];
        #pragma unroll
        for (int w = 1; w < 8; w++) mm = fmaxf(mm, smax[w]);
        g_partials[blockIdx.y * RED_X + blockIdx.x] = mm;
    }
}

// ---------------------------------------------------------------------------
// Stage 2 (fused): dt reduce -> vectorized upwind advection into smem
// -> row-factored 9-pt Laplacian (vertical strips) + RaQ -> streaming out.
// Single-use streams (u, v, Ra, out) use evict-first policy to protect
// T's 3x reuse and the maxabs u,v prefill in L2.
// ---------------------------------------------------------------------------
__global__ __launch_bounds__(THREADS)
void fused_kernel(const float* __restrict__ in, float* __restrict__ out,
                  int out_size) {
    __shared__ float sT1[P1ROWS * SPITCH];
    __shared__ float swarp[THREADS / 32];
    __shared__ float s_dt;

    const int tid = threadIdx.x;
    const int x0 = blockIdx.x * TILE_W;
    const int y0 = blockIdx.y * TILE_H;
    const int b  = blockIdx.z;

    // ---- Prologue: reduce partials -> dt ----
    {
        float m = 0.0f;
        #pragma unroll
        for (int i = 0; i < NPART / THREADS; i++)
            m = fmaxf(m, g_partials[tid + i * THREADS]);
        #pragma unroll
        for (int o = 16; o > 0; o >>= 1)
            m = fmaxf(m, __shfl_xor_sync(0xFFFFFFFFu, m, o));
        int lane = tid & 31, wid = tid >> 5;
        if (lane == 0) swarp[wid] = m;
        __syncthreads();
        if (tid == 0) {
            float mm = swarp[0];
            #pragma unroll
            for (int w = 1; w < THREADS / 32; w++) mm = fmaxf(mm, swarp[w]);
            const float dx = (float)(1.0 / 126.0);
            float dt_advect = 0.5f * 0.1f * dx / mm;
            float dx2 = dx * dx;
            float dt_diffuse = 0.5f * (dx2 * dx2) / (dx2 + dx2);
            s_dt = fminf(dt_advect, dt_diffuse);
        }
        __syncthreads();
    }
    const float dt = s_dt;

    const float dx = (float)(1.0 / 126.0);
    const float inv_dx = 1.0f / dx;

    const float* __restrict__ U  = in + (size_t)b * 4 * HW;
    const float* __restrict__ V  = U + HW;
    const float* __restrict__ T  = U + 2 * HW;
    const float* __restrict__ Ra = U + 3 * HW;

    // ---- Phase 1: advection, one float4 quad per iteration ----
    for (int q = tid; q < NQUADS; q += THREADS) {
        int ly = q / QPR;                   // 0..65
        int qi = q - ly * QPR;              // 0..33
        int gx0 = x0 - 4 + (qi << 2);       // quad's first gx (4-aligned)
        int gy = min(max(y0 - 1 + ly, 0), HH - 1);
        int ym = max(gy - 1, 0), yp = min(gy + 1, HH - 1);
        int row = gy * WW;

        float4 res;
        if (gx0 >= 1 && gx0 + 4 <= WW - 1) {
            const float4 c4 = *reinterpret_cast<const float4*>(T + row + gx0);
            const float4 t4 = *reinterpret_cast<const float4*>(T + ym * WW + gx0);
            const float4 d4 = *reinterpret_cast<const float4*>(T + yp * WW + gx0);
            const float4 u4 = __ldcs(reinterpret_cast<const float4*>(U + row + gx0));
            const float4 v4 = __ldcs(reinterpret_cast<const float4*>(V + row + gx0));
            float cl = T[row + gx0 - 1];
            float cr = T[row + gx0 + 4];

            float L[6] = {cl, c4.x, c4.y, c4.z, c4.w, cr};
            #pragma unroll
            for (int j = 0; j < 4; j++) {
                float c = L[j + 1];
                float u = (&u4.x)[j];
                float v = (&v4.x)[j];
                float t = (&t4.x)[j];
                float d = (&d4.x)[j];
                float dTdx = (u > 0.0f) ? (c - L[j]) * inv_dx
                                        : ((u < 0.0f) ? (L[j + 2] - c) * inv_dx : 0.0f);
                float dTdy = (v > 0.0f) ? (c - t) * inv_dx
                                        : ((v < 0.0f) ? (d - c) * inv_dx : 0.0f);
                (&res.x)[j] = c + dt * (-u * dTdx - v * dTdy);
            }
        } else {
            #pragma unroll
            for (int j = 0; j < 4; j++) {
                int gx = min(max(gx0 + j, 0), WW - 1);
                int xm = max(gx - 1, 0), xp = min(gx + 1, WW - 1);
                float c = T[row + gx];
                float l = T[row + xm];
                float r = T[row + xp];
                float t = T[ym * WW + gx];
                float d = T[yp * WW + gx];
                float u = U[row + gx];
                float v = V[row + gx];
                float dTdx = (u > 0.0f) ? (c - l) * inv_dx
                                        : ((u < 0.0f) ? (r - c) * inv_dx : 0.0f);
                float dTdy = (v > 0.0f) ? (c - t) * inv_dx
                                        : ((v < 0.0f) ? (d - c) * inv_dx : 0.0f);
                (&res.x)[j] = c + dt * (-u * dTdx - v * dTdy);
            }
        }
        *reinterpret_cast<float4*>(&sT1[ly * SPITCH + (qi << 2)]) = res;
    }
    __syncthreads();

    // ---- Phase 2: row-factored 9-pt Laplacian, vertical 4-row strips ----
    // lap = H(top) + 2*H(mid) + H(bot) - 16*center, H(row)=x+2y+z per column.
    {
        const float dx2 = dx * dx;
        const float lap_scale = 0.25f / dx2;
        const int cx = tid & 31;
        const int cy = tid >> 5;          // 0..15
        const int qx = cx << 2;           // 0..124
        const int qy0 = cy << 2;          // 0..60

        // Prefetch Ra for the 4 output rows (single-use: streaming loads).
        float4 ra[4];
        #pragma unroll
        for (int r = 0; r < 4; r++)
            ra[r] = __ldcs(reinterpret_cast<const float4*>(
                Ra + (size_t)(y0 + qy0 + r) * WW + (x0 + qx)));

        float* outb = out + (size_t)b * HW;

        float h_m2[4], h_m1[4], c_m1[4];
        #pragma unroll
        for (int i = 0; i < 6; i++) {
            const float* s = &sT1[(qy0 + i) * SPITCH + qx];
            float rr[12];
            *reinterpret_cast<float4*>(&rr[0]) =
                *reinterpret_cast<const float4*>(s);
            *reinterpret_cast<float4*>(&rr[4]) =
                *reinterpret_cast<const float4*>(s + 4);
            *reinterpret_cast<float4*>(&rr[8]) =
                *reinterpret_cast<const float4*>(s + 8);

            float h[4], c[4];
            #pragma unroll
            for (int jj = 0; jj < 4; jj++) {
                h[jj] = rr[jj + 3] + 2.0f * rr[jj + 4] + rr[jj + 5];
                c[jj] = rr[jj + 4];
            }

            if (i >= 2) {
                int oy = qy0 + i - 2;
                float4 res;
                #pragma unroll
                for (int jj = 0; jj < 4; jj++) {
                    float lap = h_m2[jj] + 2.0f * h_m1[jj] + h[jj]
                              - 16.0f * c_m1[jj];
                    (&res.x)[jj] = c_m1[jj]
                        + dt * (lap_scale * lap + (&ra[i - 2].x)[jj]);
                }
                __stcs(reinterpret_cast<float4*>(
                    outb + (size_t)(y0 + oy) * WW + (x0 + qx)), res);
            }
            #pragma unroll
            for (int jj = 0; jj < 4; jj++) {
                h_m2[jj] = h_m1[jj];
                h_m1[jj] = h[jj];
                c_m1[jj] = c[jj];
            }
        }
    }

    if (tid == 0 && blockIdx.x == 0 && blockIdx.y == 0 && blockIdx.z == 0) {
        out[out_size - 1] = dt;
    }
}

extern "C" void kernel_launch(void* const* d_in, const int* in_sizes, int n_in,
                              void* d_out, int out_size) {
    const float* in = (const float*)d_in[0];
    float* out = (float*)d_out;

    dim3 rgrid(RED_X, BATCH);
    maxabs_kernel<<<rgrid, 256>>>(in);

    dim3 fgrid(WW / TILE_W, HH / TILE_H, BATCH);  // 8 x 16 x 16 = 2048
    fused_kernel<<<fgrid, THREADS>>>(in, out, out_size);
}

// round 10
// speedup vs baseline: 1.1275x; 1.1275x over previous
#include <cuda_runtime.h>
#include <cstdint>

// Geometry fixed by setup_inputs: (16, 4, 1024, 1024) float32
#define BATCH 16
#define HH 1024
#define WW 1024
#define HW (HH * WW)

#define TILE_W 128
#define TILE_H 64
#define THREADS 512

// Phase-1 T1 region: rows gy = y0-1 .. y0+64 (66), cols gx = x0-4 .. x0+131
// (34 quads of 4). Pitch 136 floats, float4-aligned.
#define P1ROWS (TILE_H + 2)        // 66
#define QPR 34                     // quads per row
#define SPITCH (QPR * 4)           // 136
#define NQUADS (P1ROWS * QPR)      // 2244

#define RED_X 128
#define NPART (RED_X * BATCH)      // 2048 partials

__device__ float g_partials[NPART];

// ---------------------------------------------------------------------------
// Stage 1: per-block max(|u|,|v|) partials (unconditional writes, no reset).
// ---------------------------------------------------------------------------
__global__ __launch_bounds__(256)
void maxabs_kernel(const float* __restrict__ in) {
    const float4* __restrict__ base =
        reinterpret_cast<const float4*>(in + (size_t)blockIdx.y * 4 * HW);
    const int n4 = 2 * HW / 4;
    float m = 0.0f;
    #pragma unroll 8
    for (int i = blockIdx.x * 256 + threadIdx.x; i < n4; i += RED_X * 256) {
        float4 vv = base[i];
        m = fmaxf(m, fabsf(vv.x));
        m = fmaxf(m, fabsf(vv.y));
        m = fmaxf(m, fabsf(vv.z));
        m = fmaxf(m, fabsf(vv.w));
    }
    #pragma unroll
    for (int o = 16; o > 0; o >>= 1)
        m = fmaxf(m, __shfl_xor_sync(0xFFFFFFFFu, m, o));
    __shared__ float smax[8];
    int lane = threadIdx.x & 31, wid = threadIdx.x >> 5;
    if (lane == 0) smax[wid] = m;
    __syncthreads();
    if (threadIdx.x == 0) {
        float mm = smax[0];
        #pragma unroll
        for (int w = 1; w < 8; w++) mm = fmaxf(mm, smax[w]);
        g_partials[blockIdx.y * RED_X + blockIdx.x] = mm;
    }
}

// ---------------------------------------------------------------------------
// Stage 2 (fused): dt reduce -> vectorized upwind advection into smem
// -> row-factored 9-pt Laplacian (vertical strips) + RaQ -> float4 out.
// __launch_bounds__(512,4): cap regs at 32 so 4 blocks/SM co-reside.
// ---------------------------------------------------------------------------
__global__ __launch_bounds__(THREADS, 4)
void fused_kernel(const float* __restrict__ in, float* __restrict__ out,
                  int out_size) {
    __shared__ float sT1[P1ROWS * SPITCH];
    __shared__ float swarp[THREADS / 32];
    __shared__ float s_dt;

    const int tid = threadIdx.x;
    const int x0 = blockIdx.x * TILE_W;
    const int y0 = blockIdx.y * TILE_H;
    const int b  = blockIdx.z;

    // ---- Prologue: reduce partials -> dt ----
    {
        float m = 0.0f;
        #pragma unroll
        for (int i = 0; i < NPART / THREADS; i++)
            m = fmaxf(m, g_partials[tid + i * THREADS]);
        #pragma unroll
        for (int o = 16; o > 0; o >>= 1)
            m = fmaxf(m, __shfl_xor_sync(0xFFFFFFFFu, m, o));
        int lane = tid & 31, wid = tid >> 5;
        if (lane == 0) swarp[wid] = m;
        __syncthreads();
        if (tid == 0) {
            float mm = swarp[0];
            #pragma unroll
            for (int w = 1; w < THREADS / 32; w++) mm = fmaxf(mm, swarp[w]);
            const float dx = (float)(1.0 / 126.0);
            float dt_advect = 0.5f * 0.1f * dx / mm;
            float dx2 = dx * dx;
            float dt_diffuse = 0.5f * (dx2 * dx2) / (dx2 + dx2);
            s_dt = fminf(dt_advect, dt_diffuse);
        }
        __syncthreads();
    }
    const float dt = s_dt;

    const float dx = (float)(1.0 / 126.0);
    const float inv_dx = 1.0f / dx;

    const float* __restrict__ U  = in + (size_t)b * 4 * HW;
    const float* __restrict__ V  = U + HW;
    const float* __restrict__ T  = U + 2 * HW;
    const float* __restrict__ Ra = U + 3 * HW;

    // ---- Phase 1: advection, one float4 quad per iteration ----
    for (int q = tid; q < NQUADS; q += THREADS) {
        int ly = q / QPR;                   // 0..65
        int qi = q - ly * QPR;              // 0..33
        int gx0 = x0 - 4 + (qi << 2);       // quad's first gx (4-aligned)
        int gy = min(max(y0 - 1 + ly, 0), HH - 1);
        int ym = max(gy - 1, 0), yp = min(gy + 1, HH - 1);
        int row = gy * WW;

        float4 res;
        if (gx0 >= 1 && gx0 + 4 <= WW - 1) {
            const float4 c4 = *reinterpret_cast<const float4*>(T + row + gx0);
            const float4 t4 = *reinterpret_cast<const float4*>(T + ym * WW + gx0);
            const float4 d4 = *reinterpret_cast<const float4*>(T + yp * WW + gx0);
            const float4 u4 = *reinterpret_cast<const float4*>(U + row + gx0);
            const float4 v4 = *reinterpret_cast<const float4*>(V + row + gx0);
            float cl = T[row + gx0 - 1];
            float cr = T[row + gx0 + 4];

            float L[6] = {cl, c4.x, c4.y, c4.z, c4.w, cr};
            #pragma unroll
            for (int j = 0; j < 4; j++) {
                float c = L[j + 1];
                float u = (&u4.x)[j];
                float v = (&v4.x)[j];
                float t = (&t4.x)[j];
                float d = (&d4.x)[j];
                float dTdx = (u > 0.0f) ? (c - L[j]) * inv_dx
                                        : ((u < 0.0f) ? (L[j + 2] - c) * inv_dx : 0.0f);
                float dTdy = (v > 0.0f) ? (c - t) * inv_dx
                                        : ((v < 0.0f) ? (d - c) * inv_dx : 0.0f);
                (&res.x)[j] = c + dt * (-u * dTdx - v * dTdy);
            }
        } else {
            #pragma unroll
            for (int j = 0; j < 4; j++) {
                int gx = min(max(gx0 + j, 0), WW - 1);
                int xm = max(gx - 1, 0), xp = min(gx + 1, WW - 1);
                float c = T[row + gx];
                float l = T[row + xm];
                float r = T[row + xp];
                float t = T[ym * WW + gx];
                float d = T[yp * WW + gx];
                float u = U[row + gx];
                float v = V[row + gx];
                float dTdx = (u > 0.0f) ? (c - l) * inv_dx
                                        : ((u < 0.0f) ? (r - c) * inv_dx : 0.0f);
                float dTdy = (v > 0.0f) ? (c - t) * inv_dx
                                        : ((v < 0.0f) ? (d - c) * inv_dx : 0.0f);
                (&res.x)[j] = c + dt * (-u * dTdx - v * dTdy);
            }
        }
        *reinterpret_cast<float4*>(&sT1[ly * SPITCH + (qi << 2)]) = res;
    }
    __syncthreads();

    // ---- Phase 2: row-factored 9-pt Laplacian, vertical 4-row strips ----
    // lap = H(top) + 2*H(mid) + H(bot) - 16*center, H(row)=x+2y+z per column.
    // Ra loaded in-loop (not prefetched) to keep register count <= 32.
    {
        const float dx2 = dx * dx;
        const float lap_scale = 0.25f / dx2;
        const int cx = tid & 31;
        const int cy = tid >> 5;          // 0..15
        const int qx = cx << 2;           // 0..124
        const int qy0 = cy << 2;          // 0..60

        float* outb = out + (size_t)b * HW;

        float h_m2[4], h_m1[4], c_m1[4];
        #pragma unroll
        for (int i = 0; i < 6; i++) {
            const float* s = &sT1[(qy0 + i) * SPITCH + qx];
            float rr[12];
            *reinterpret_cast<float4*>(&rr[0]) =
                *reinterpret_cast<const float4*>(s);
            *reinterpret_cast<float4*>(&rr[4]) =
                *reinterpret_cast<const float4*>(s + 4);
            *reinterpret_cast<float4*>(&rr[8]) =
                *reinterpret_cast<const float4*>(s + 8);

            float h[4], c[4];
            #pragma unroll
            for (int jj = 0; jj < 4; jj++) {
                h[jj] = rr[jj + 3] + 2.0f * rr[jj + 4] + rr[jj + 5];
                c[jj] = rr[jj + 4];
            }

            if (i >= 2) {
                int oy = qy0 + i - 2;
                float4 ra = *reinterpret_cast<const float4*>(
                    Ra + (size_t)(y0 + oy) * WW + (x0 + qx));
                float4 res;
                #pragma unroll
                for (int jj = 0; jj < 4; jj++) {
                    float lap = h_m2[jj] + 2.0f * h_m1[jj] + h[jj]
                              - 16.0f * c_m1[jj];
                    (&res.x)[jj] = c_m1[jj]
                        + dt * (lap_scale * lap + (&ra.x)[jj]);
                }
                *reinterpret_cast<float4*>(
                    outb + (size_t)(y0 + oy) * WW + (x0 + qx)) = res;
            }
            #pragma unroll
            for (int jj = 0; jj < 4; jj++) {
                h_m2[jj] = h_m1[jj];
                h_m1[jj] = h[jj];
                c_m1[jj] = c[jj];
            }
        }
    }

    if (tid == 0 && blockIdx.x == 0 && blockIdx.y == 0 && blockIdx.z == 0) {
        out[out_size - 1] = dt;
    }
}

extern "C" void kernel_launch(void* const* d_in, const int* in_sizes, int n_in,
                              void* d_out, int out_size) {
    const float* in = (const float*)d_in[0];
    float* out = (float*)d_out;

    dim3 rgrid(RED_X, BATCH);
    maxabs_kernel<<<rgrid, 256>>>(in);

    dim3 fgrid(WW / TILE_W, HH / TILE_H, BATCH);  // 8 x 16 x 16 = 2048
    fused_kernel<<<fgrid, THREADS>>>(in, out, out_size);
}

// round 11
// speedup vs baseline: 1.2437x; 1.1031x over previous
#include <cuda_runtime.h>
#include <cstdint>

// Geometry fixed by setup_inputs: (16, 4, 1024, 1024) float32
#define BATCH 16
#define HH 1024
#define WW 1024
#define HW (HH * WW)

#define TILE_W 128
#define TILE_H 32
#define THREADS 256

// Phase-1 T1 region: rows gy = y0-1 .. y0+32 (34), cols gx = x0-4 .. x0+131
// (34 quads of 4). Pitch 136 floats, float4-aligned.
#define P1ROWS (TILE_H + 2)        // 34
#define QPR 34                     // quads per row
#define SPITCH (QPR * 4)           // 136
#define NQUADS (P1ROWS * QPR)      // 1156

#define RED_X 128
#define NPART (RED_X * BATCH)      // 2048 partials

__device__ float g_partials[NPART];

// ---------------------------------------------------------------------------
// Stage 1: per-block max(|u|,|v|) partials (unconditional writes, no reset).
// ---------------------------------------------------------------------------
__global__ __launch_bounds__(256)
void maxabs_kernel(const float* __restrict__ in) {
    const float4* __restrict__ base =
        reinterpret_cast<const float4*>(in + (size_t)blockIdx.y * 4 * HW);
    const int n4 = 2 * HW / 4;
    float m = 0.0f;
    #pragma unroll 8
    for (int i = blockIdx.x * 256 + threadIdx.x; i < n4; i += RED_X * 256) {
        float4 vv = base[i];
        m = fmaxf(m, fabsf(vv.x));
        m = fmaxf(m, fabsf(vv.y));
        m = fmaxf(m, fabsf(vv.z));
        m = fmaxf(m, fabsf(vv.w));
    }
    #pragma unroll
    for (int o = 16; o > 0; o >>= 1)
        m = fmaxf(m, __shfl_xor_sync(0xFFFFFFFFu, m, o));
    __shared__ float smax[8];
    int lane = threadIdx.x & 31, wid = threadIdx.x >> 5;
    if (lane == 0) smax[wid] = m;
    __syncthreads();
    if (threadIdx.x == 0) {
        float mm = smax[0];
        #pragma unroll
        for (int w = 1; w < 8; w++) mm = fmaxf(mm, smax[w]);
        g_partials[blockIdx.y * RED_X + blockIdx.x] = mm;
    }
}

// ---------------------------------------------------------------------------
// Stage 2 (fused): dt reduce -> vectorized upwind advection into smem
// -> row-factored 9-pt Laplacian (vertical strips) + RaQ -> float4 out.
// 256-thread blocks on 128x32 tiles: ~6 independent blocks/SM so barrier
// and prologue stalls of one block are hidden by the others.
// ---------------------------------------------------------------------------
__global__ __launch_bounds__(THREADS)
void fused_kernel(const float* __restrict__ in, float* __restrict__ out,
                  int out_size) {
    __shared__ float sT1[P1ROWS * SPITCH];
    __shared__ float swarp[THREADS / 32];
    __shared__ float s_dt;

    const int tid = threadIdx.x;
    const int x0 = blockIdx.x * TILE_W;
    const int y0 = blockIdx.y * TILE_H;
    const int b  = blockIdx.z;

    // ---- Prologue: reduce partials -> dt ----
    {
        float m = 0.0f;
        #pragma unroll
        for (int i = 0; i < NPART / THREADS; i++)
            m = fmaxf(m, g_partials[tid + i * THREADS]);
        #pragma unroll
        for (int o = 16; o > 0; o >>= 1)
            m = fmaxf(m, __shfl_xor_sync(0xFFFFFFFFu, m, o));
        int lane = tid & 31, wid = tid >> 5;
        if (lane == 0) swarp[wid] = m;
        __syncthreads();
        if (tid == 0) {
            float mm = swarp[0];
            #pragma unroll
            for (int w = 1; w < THREADS / 32; w++) mm = fmaxf(mm, swarp[w]);
            const float dx = (float)(1.0 / 126.0);
            float dt_advect = 0.5f * 0.1f * dx / mm;
            float dx2 = dx * dx;
            float dt_diffuse = 0.5f * (dx2 * dx2) / (dx2 + dx2);
            s_dt = fminf(dt_advect, dt_diffuse);
        }
        __syncthreads();
    }
    const float dt = s_dt;

    const float dx = (float)(1.0 / 126.0);
    const float inv_dx = 1.0f / dx;

    const float* __restrict__ U  = in + (size_t)b * 4 * HW;
    const float* __restrict__ V  = U + HW;
    const float* __restrict__ T  = U + 2 * HW;
    const float* __restrict__ Ra = U + 3 * HW;

    // ---- Phase 1: advection, one float4 quad per iteration ----
    for (int q = tid; q < NQUADS; q += THREADS) {
        int ly = q / QPR;                   // 0..33
        int qi = q - ly * QPR;              // 0..33
        int gx0 = x0 - 4 + (qi << 2);       // quad's first gx (4-aligned)
        int gy = min(max(y0 - 1 + ly, 0), HH - 1);
        int ym = max(gy - 1, 0), yp = min(gy + 1, HH - 1);
        int row = gy * WW;

        float4 res;
        if (gx0 >= 1 && gx0 + 4 <= WW - 1) {
            const float4 c4 = *reinterpret_cast<const float4*>(T + row + gx0);
            const float4 t4 = *reinterpret_cast<const float4*>(T + ym * WW + gx0);
            const float4 d4 = *reinterpret_cast<const float4*>(T + yp * WW + gx0);
            const float4 u4 = *reinterpret_cast<const float4*>(U + row + gx0);
            const float4 v4 = *reinterpret_cast<const float4*>(V + row + gx0);
            float cl = T[row + gx0 - 1];
            float cr = T[row + gx0 + 4];

            float L[6] = {cl, c4.x, c4.y, c4.z, c4.w, cr};
            #pragma unroll
            for (int j = 0; j < 4; j++) {
                float c = L[j + 1];
                float u = (&u4.x)[j];
                float v = (&v4.x)[j];
                float t = (&t4.x)[j];
                float d = (&d4.x)[j];
                float dTdx = (u > 0.0f) ? (c - L[j]) * inv_dx
                                        : ((u < 0.0f) ? (L[j + 2] - c) * inv_dx : 0.0f);
                float dTdy = (v > 0.0f) ? (c - t) * inv_dx
                                        : ((v < 0.0f) ? (d - c) * inv_dx : 0.0f);
                (&res.x)[j] = c + dt * (-u * dTdx - v * dTdy);
            }
        } else {
            #pragma unroll
            for (int j = 0; j < 4; j++) {
                int gx = min(max(gx0 + j, 0), WW - 1);
                int xm = max(gx - 1, 0), xp = min(gx + 1, WW - 1);
                float c = T[row + gx];
                float l = T[row + xm];
                float r = T[row + xp];
                float t = T[ym * WW + gx];
                float d = T[yp * WW + gx];
                float u = U[row + gx];
                float v = V[row + gx];
                float dTdx = (u > 0.0f) ? (c - l) * inv_dx
                                        : ((u < 0.0f) ? (r - c) * inv_dx : 0.0f);
                float dTdy = (v > 0.0f) ? (c - t) * inv_dx
                                        : ((v < 0.0f) ? (d - c) * inv_dx : 0.0f);
                (&res.x)[j] = c + dt * (-u * dTdx - v * dTdy);
            }
        }
        *reinterpret_cast<float4*>(&sT1[ly * SPITCH + (qi << 2)]) = res;
    }
    __syncthreads();

    // ---- Phase 2: row-factored 9-pt Laplacian, vertical 4-row strips ----
    // lap = H(top) + 2*H(mid) + H(bot) - 16*center, H(row)=x+2y+z per column.
    {
        const float dx2 = dx * dx;
        const float lap_scale = 0.25f / dx2;
        const int cx = tid & 31;
        const int cy = tid >> 5;          // 0..7
        const int qx = cx << 2;           // 0..124
        const int qy0 = cy << 2;          // 0..28

        float* outb = out + (size_t)b * HW;

        float h_m2[4], h_m1[4], c_m1[4];
        #pragma unroll
        for (int i = 0; i < 6; i++) {
            const float* s = &sT1[(qy0 + i) * SPITCH + qx];
            float rr[12];
            *reinterpret_cast<float4*>(&rr[0]) =
                *reinterpret_cast<const float4*>(s);
            *reinterpret_cast<float4*>(&rr[4]) =
                *reinterpret_cast<const float4*>(s + 4);
            *reinterpret_cast<float4*>(&rr[8]) =
                *reinterpret_cast<const float4*>(s + 8);

            float h[4], c[4];
            #pragma unroll
            for (int jj = 0; jj < 4; jj++) {
                h[jj] = rr[jj + 3] + 2.0f * rr[jj + 4] + rr[jj + 5];
                c[jj] = rr[jj + 4];
            }

            if (i >= 2) {
                int oy = qy0 + i - 2;
                float4 ra = *reinterpret_cast<const float4*>(
                    Ra + (size_t)(y0 + oy) * WW + (x0 + qx));
                float4 res;
                #pragma unroll
                for (int jj = 0; jj < 4; jj++) {
                    float lap = h_m2[jj] + 2.0f * h_m1[jj] + h[jj]
                              - 16.0f * c_m1[jj];
                    (&res.x)[jj] = c_m1[jj]
                        + dt * (lap_scale * lap + (&ra.x)[jj]);
                }
                *reinterpret_cast<float4*>(
                    outb + (size_t)(y0 + oy) * WW + (x0 + qx)) = res;
            }
            #pragma unroll
            for (int jj = 0; jj < 4; jj++) {
                h_m2[jj] = h_m1[jj];
                h_m1[jj] = h[jj];
                c_m1[jj] = c[jj];
            }
        }
    }

    if (tid == 0 && blockIdx.x == 0 && blockIdx.y == 0 && blockIdx.z == 0) {
        out[out_size - 1] = dt;
    }
}

extern "C" void kernel_launch(void* const* d_in, const int* in_sizes, int n_in,
                              void* d_out, int out_size) {
    const float* in = (const float*)d_in[0];
    float* out = (float*)d_out;

    dim3 rgrid(RED_X, BATCH);
    maxabs_kernel<<<rgrid, 256>>>(in);

    dim3 fgrid(WW / TILE_W, HH / TILE_H, BATCH);  // 8 x 32 x 16 = 4096
    fused_kernel<<<fgrid, THREADS>>>(in, out, out_size);
}